// round 2
// baseline (speedup 1.0000x reference)
#include <cuda_runtime.h>
#include <math.h>

// PennyLaneBasicDQN: 16-qubit VQC (RY embed + 4x[Rot,CZ]) + linear head.
// Exact light-cone method: z_i depends only on wires [i-3, i+3] (final CZ layer
// is diagonal -> dropped; straddling CZs commute out). Each (sample,qubit)
// problem is an exact <=7-qubit simulation done by a 4-thread quad:
// 32 complex amplitudes per thread in registers, quad bits via shfl.xor.

#define NQ 16
#define NA 6
#define BATCHSZ 512

__device__ __forceinline__ float2 cmul(float2 a, float2 b) {
    return make_float2(a.x * b.x - a.y * b.y, a.x * b.y + a.y * b.x);
}
__device__ __forceinline__ float2 cadd(float2 a, float2 b) {
    return make_float2(a.x + b.x, a.y + b.y);
}

__global__ __launch_bounds__(128)
void dqn_lightcone_kernel(const float* __restrict__ x,
                          const float* __restrict__ W,
                          const float* __restrict__ fcw,
                          const float* __restrict__ fcb,
                          float* __restrict__ out)
{
    // mats[l][w][e]: Rot(weights[l,w]) 2x2 complex, e in {00,01,10,11}
    __shared__ float2 mats[4][16][4];
    __shared__ float xs[2][16];
    __shared__ float zres[2][16];

    const int tid = threadIdx.x;
    const int b0  = blockIdx.x * 2;   // 2 samples per CTA

    // --- build the 64 Rot matrices (batch-independent) ---
    if (tid < 64) {
        int l = tid >> 4, w = tid & 15;
        const float* wp = W + ((l * 16 + w) * 3);
        float phi = wp[0], th = wp[1], om = wp[2];
        float c, s;
        sincosf(0.5f * th, &s, &c);
        float epx, epy, emx, emy;
        sincosf(-0.5f * (phi + om), &epy, &epx);   // ep = exp(-i(phi+om)/2)
        sincosf(-0.5f * (phi - om), &emy, &emx);   // em = exp(-i(phi-om)/2)
        mats[l][w][0] = make_float2( epx * c,  epy * c);   // m00 = ep*c
        mats[l][w][1] = make_float2(-emx * s,  emy * s);   // m01 = -conj(em)*s
        mats[l][w][2] = make_float2( emx * s,  emy * s);   // m10 = em*s
        mats[l][w][3] = make_float2( epx * c, -epy * c);   // m11 = conj(ep)*c
    }
    if (tid < 32) {
        xs[tid >> 4][tid & 15] = x[(b0 + (tid >> 4)) * NQ + (tid & 15)];
    }
    __syncthreads();

    const int p  = tid >> 2;      // problem within CTA: 0..31
    const int bl = p >> 4;        // local sample 0/1
    const int i  = p & 15;        // measured qubit
    const int q  = tid & 3;       // quad lane -> amplitude bits 5,6

    // per-wire post-(RY,Rot0) 2-vectors; padded wires -> |0>
    float2 u0[7], u1[7];
    #pragma unroll
    for (int k = 0; k < 7; k++) {
        int w = i - 3 + k;
        if (w >= 0 && w < NQ) {
            float c, s;
            sincosf(0.5f * xs[bl][w], &s, &c);
            float2 a = mats[0][w][0], b = mats[0][w][1];
            float2 d = mats[0][w][2], e = mats[0][w][3];
            u0[k] = make_float2(a.x * c + b.x * s, a.y * c + b.y * s);
            u1[k] = make_float2(d.x * c + e.x * s, d.y * c + e.y * s);
        } else {
            u0[k] = make_float2(1.f, 0.f);
            u1[k] = make_float2(0.f, 0.f);
        }
    }

    // init product state: bit k of amplitude index = window wire i-3+k
    float2 st[32];
    {
        float2 b5 = (q & 1) ? u1[5] : u0[5];
        float2 b6 = (q & 2) ? u1[6] : u0[6];
        st[0] = cmul(b5, b6);
    }
    #pragma unroll
    for (int k = 0; k < 5; k++) {
        #pragma unroll
        for (int j = 0; j < 16; j++) {
            if (j < (1 << k)) {
                float2 a = st[j];
                st[j | (1 << k)] = cmul(a, u1[k]);
                st[j]            = cmul(a, u0[k]);
            }
        }
    }

    // CZ sign mask: pair k couples bits (k,k+1) iff both wires in [0,15]
    unsigned pairmask = 0;
    #pragma unroll
    for (int k = 0; k < 6; k++) {
        int w = i - 3 + k;
        if (w >= 0 && (w + 1) < NQ) pairmask |= 1u << k;
    }
    unsigned czneg = 0;   // bit j: odd # of adjacent-11 pairs for index (q<<5)|j
    #pragma unroll
    for (int j = 0; j < 32; j++) {
        unsigned m = ((unsigned)q << 5) | (unsigned)j;
        if (__popc(m & (m >> 1) & pairmask) & 1) czneg |= 1u << j;
    }

    // sequence: CZ, Rot1, CZ, Rot2, CZ, Rot3
    #pragma unroll
    for (int l = 1; l < 4; l++) {
        // CZ chain
        #pragma unroll
        for (int j = 0; j < 32; j++) {
            float sg = ((czneg >> j) & 1) ? -1.f : 1.f;
            st[j].x *= sg; st[j].y *= sg;
        }
        // Rot layer l on all window wires
        #pragma unroll
        for (int k = 0; k < 7; k++) {
            int w = i - 3 + k;
            float2 m00, m01, m10, m11;
            if (w >= 0 && w < NQ) {
                m00 = mats[l][w][0]; m01 = mats[l][w][1];
                m10 = mats[l][w][2]; m11 = mats[l][w][3];
            } else {
                m00 = make_float2(1.f, 0.f); m01 = make_float2(0.f, 0.f);
                m10 = make_float2(0.f, 0.f); m11 = make_float2(1.f, 0.f);
            }
            if (k < 5) {
                const int n = 1 << k;
                #pragma unroll
                for (int j = 0; j < 32; j++) {
                    if (!(j & n)) {
                        float2 a0 = st[j], a1 = st[j | n];
                        st[j]     = cadd(cmul(m00, a0), cmul(m01, a1));
                        st[j | n] = cadd(cmul(m10, a0), cmul(m11, a1));
                    }
                }
            } else {
                const int tb    = 1 << (k - 5);
                const int mybit = (q >> (k - 5)) & 1;
                float2 ma = mybit ? m11 : m00;   // M[b][b]
                float2 mb = mybit ? m10 : m01;   // M[b][1-b]
                #pragma unroll
                for (int j = 0; j < 32; j++) {
                    float2 o;
                    o.x = __shfl_xor_sync(0xffffffffu, st[j].x, tb);
                    o.y = __shfl_xor_sync(0xffffffffu, st[j].y, tb);
                    st[j] = cadd(cmul(ma, st[j]), cmul(mb, o));
                }
            }
        }
    }

    // <Z_i>: sign from bit 3 (center wire); bit 3 lives in local index j
    float z = 0.f;
    #pragma unroll
    for (int j = 0; j < 32; j++) {
        float p2 = st[j].x * st[j].x + st[j].y * st[j].y;
        z += (j & 8) ? -p2 : p2;
    }
    z += __shfl_xor_sync(0xffffffffu, z, 1);
    z += __shfl_xor_sync(0xffffffffu, z, 2);
    if (q == 0) zres[bl][i] = z;
    __syncthreads();

    // fused FC head: out[b,a] = fc_b[a] + sum_i z[b,i]*fc_w[a,i]
    if (tid < 2 * NA) {
        int bb = tid / NA, a = tid % NA;
        float acc = fcb[a];
        #pragma unroll
        for (int ii = 0; ii < NQ; ii++)
            acc += zres[bb][ii] * fcw[a * NQ + ii];
        out[(b0 + bb) * NA + a] = acc;
    }
}

extern "C" void kernel_launch(void* const* d_in, const int* in_sizes, int n_in,
                              void* d_out, int out_size) {
    const float* x   = (const float*)d_in[0];   // [512,16]
    const float* W   = (const float*)d_in[1];   // [4,16,3]
    const float* fcw = (const float*)d_in[2];   // [6,16]
    const float* fcb = (const float*)d_in[3];   // [6]
    float* out = (float*)d_out;                 // [512,6]
    (void)in_sizes; (void)n_in; (void)out_size;
    dqn_lightcone_kernel<<<BATCHSZ / 2, 128>>>(x, W, fcw, fcb, out);
}

// round 3
// speedup vs baseline: 1.8168x; 1.8168x over previous
#include <cuda_runtime.h>
#include <math.h>

// PennyLaneBasicDQN: 16-qubit VQC (RY embed + 4x[Rot,CZ chain]) + linear head.
// Heisenberg light-cone + Pauli-transfer-matrix method:
//   z_i = <psi1| W^dag Z_i W |psi1>,  psi1 = Rot0*RY(x)|0> (product state),
//   W = D2 R3 ... actually W = R3 D2 R2 D1 R1 D0 (final CZ layer D3 dropped:
//   diagonal, does not change probabilities).
// Backward support of Z_i is wires [i-2,i+2]; D0's straddling CZs reduce
// exactly to scaling X/Y Pauli components of window edges by mz of wire i-/+3.
// T_i (1024 real Pauli coeffs) is batch-shared; per sample only a cheap
// contraction against per-wire Bloch 4-vectors remains.

#define NQ 16
#define NA 6
#define BATCHSZ 512

__device__ float g_z[BATCHSZ * NQ];

struct C2 { float x, y; };
__device__ __forceinline__ C2 cmk(float a, float b){ C2 r; r.x=a; r.y=b; return r; }
__device__ __forceinline__ C2 cml(C2 a, C2 b){ return cmk(a.x*b.x - a.y*b.y, a.x*b.y + a.y*b.x); }
__device__ __forceinline__ C2 cad(C2 a, C2 b){ return cmk(a.x+b.x, a.y+b.y); }

// 4x4 real PTM of conjugation O -> U^dag O U:
//   M[q][p] = 0.5 * Re Tr[ sigma_q U^dag sigma_p U ]
__device__ void ptm_from_u(const C2 u[4], float* M) {
    C2 ud00 = cmk(u[0].x, -u[0].y), ud01 = cmk(u[2].x, -u[2].y);
    C2 ud10 = cmk(u[1].x, -u[1].y), ud11 = cmk(u[3].x, -u[3].y);
    #pragma unroll
    for (int p = 0; p < 4; p++) {
        C2 s00, s01, s10, s11;                 // sigma_p * U
        if (p == 0)      { s00=u[0]; s01=u[1]; s10=u[2]; s11=u[3]; }
        else if (p == 1) { s00=u[2]; s01=u[3]; s10=u[0]; s11=u[1]; }
        else if (p == 2) {                      // Y = [[0,-i],[i,0]]
            s00 = cmk( u[2].y, -u[2].x);        // -i*u10
            s01 = cmk( u[3].y, -u[3].x);
            s10 = cmk(-u[0].y,  u[0].x);        //  i*u00
            s11 = cmk(-u[1].y,  u[1].x);
        } else           { s00=u[0]; s01=u[1]; s10=cmk(-u[2].x,-u[2].y); s11=cmk(-u[3].x,-u[3].y); }
        C2 A00 = cad(cml(ud00, s00), cml(ud01, s10));
        C2 A01 = cad(cml(ud00, s01), cml(ud01, s11));
        C2 A10 = cad(cml(ud10, s00), cml(ud11, s10));
        C2 A11 = cad(cml(ud10, s01), cml(ud11, s11));
        M[0*4+p] = 0.5f*(A00.x + A11.x);
        M[1*4+p] = 0.5f*(A01.x + A10.x);
        M[2*4+p] = 0.5f*(A10.y - A01.y);        // Re(i*(A01-A10))
        M[3*4+p] = 0.5f*(A00.x - A11.x);
    }
}

// PennyLane Rot(phi,theta,omega) = RZ(omega) RY(theta) RZ(phi)
__device__ __forceinline__ void rot_u(const float* wp, C2 u[4]) {
    float phi = wp[0], th = wp[1], om = wp[2];
    float c, s; sincosf(0.5f*th, &s, &c);
    float epx, epy, emx, emy;
    sincosf(-0.5f*(phi+om), &epy, &epx);   // ep = exp(-i(phi+om)/2)
    sincosf(-0.5f*(phi-om), &emy, &emx);   // em = exp(-i(phi-om)/2)
    u[0] = cmk( epx*c,  epy*c);            // m00 = ep*c
    u[1] = cmk(-emx*s,  emy*s);            // m01 = -conj(em)*s
    u[2] = cmk( emx*s,  emy*s);            // m10 = em*s
    u[3] = cmk( epx*c, -epy*c);            // m11 = conj(ep)*c
}

__global__ __launch_bounds__(128)
void vqc_main(const float* __restrict__ x, const float* __restrict__ W)
{
    __shared__ __align__(16) float tA[1024];
    __shared__ __align__(16) float tB[1024];
    __shared__ float PT[15][16];       // conj-PTMs: layers 1..3 x window pos 0..4
    __shared__ float bx[7][3], bz[7][3];  // Bloch transform cols for wires i-3..i+3

    const int i   = blockIdx.x;        // measured qubit
    const int tid = threadIdx.x;

    if (tid < 15) {
        int l = 1 + tid / 5, a = tid % 5;
        int w = i - 2 + a;
        float* M = PT[tid];
        if (w >= 0 && w < NQ) {
            C2 u[4]; rot_u(W + (l*NQ + w)*3, u);
            ptm_from_u(u, M);
        } else {
            #pragma unroll
            for (int k = 0; k < 16; k++) M[k] = (k % 5 == 0) ? 1.f : 0.f;
        }
    } else if (tid >= 16 && tid < 23) {
        int k = tid - 16;
        int w = i - 3 + k;
        if (w >= 0 && w < NQ) {
            C2 u[4]; rot_u(W + w*3, u);                    // layer-0 Rot
            C2 v[4] = { cmk(u[0].x,-u[0].y), cmk(u[2].x,-u[2].y),
                        cmk(u[1].x,-u[1].y), cmk(u[3].x,-u[3].y) };  // U^dag
            float N[16]; ptm_from_u(v, N);                 // forward Bloch PTM
            bx[k][0]=N[4+1]; bx[k][1]=N[8+1]; bx[k][2]=N[12+1];
            bz[k][0]=N[4+3]; bz[k][1]=N[8+3]; bz[k][2]=N[12+3];
        } else {
            bx[k][0]=bx[k][1]=bx[k][2]=0.f;
            bz[k][0]=bz[k][1]=bz[k][2]=0.f;
        }
    }
    for (int j = tid; j < 1024; j += 128) tA[j] = (j == 48) ? 1.f : 0.f; // Z at pos 2
    __syncthreads();

    // Backward conjugation: M(R3), CZ(D2), M(R2), CZ(D1), M(R1), CZ(D0)
    float* src = tA; float* dst = tB;
    for (int l = 3; l >= 1; l--) {
        for (int a = 0; a < 5; a++) {
            const float* M = PT[(l-1)*5 + a];
            const int s = 1 << (2*(4-a));      // axis stride: 256,64,16,4,1
            for (int g = tid; g < 256; g += 128) {
                int base = (g / s) * (4*s) + (g % s);
                float c0 = src[base], c1 = src[base+s], c2 = src[base+2*s], c3 = src[base+3*s];
                dst[base]     = M[0] *c0 + M[1] *c1 + M[2] *c2 + M[3] *c3;
                dst[base+s]   = M[4] *c0 + M[5] *c1 + M[6] *c2 + M[7] *c3;
                dst[base+2*s] = M[8] *c0 + M[9] *c1 + M[10]*c2 + M[11]*c3;
                dst[base+3*s] = M[12]*c0 + M[13]*c1 + M[14]*c2 + M[15]*c3;
            }
            __syncthreads();
            float* t = src; src = dst; dst = t;
        }
        // CZ chain on window pairs (pos a, a+1) where both wires exist.
        // CZ Pauli map: np = xr? p^3:p ; nq = xl? q^3:q ; sign -1 iff xl&&xr&&p!=q
        for (int e = tid; e < 1024; e += 128) {
            int p0=(e>>8)&3, p1=(e>>6)&3, p2=(e>>4)&3, p3=(e>>2)&3, p4=e&3;
            int p[5] = {p0,p1,p2,p3,p4};
            float sg = src[e];
            #pragma unroll
            for (int a = 0; a < 4; a++) {
                int wl = i - 2 + a;
                if (wl >= 0 && wl + 1 < NQ) {
                    int pa = p[a], pb = p[a+1];
                    bool xl = (pa==1)||(pa==2), xr = (pb==1)||(pb==2);
                    if (xl && xr && pa != pb) sg = -sg;
                    if (xr) p[a]   = pa ^ 3;
                    if (xl) p[a+1] = pb ^ 3;
                }
            }
            int di = (p[0]<<8)|(p[1]<<6)|(p[2]<<4)|(p[3]<<2)|p[4];
            dst[di] = sg;
        }
        __syncthreads();
        float* t = src; src = dst; dst = t;
    }
    // 18 stages (even) -> final tensor in `src`

    // ---- per-sample contraction ----
    const int b = blockIdx.y * 128 + tid;
    float m[7][3];
    #pragma unroll
    for (int k = 0; k < 7; k++) {
        int w = i - 3 + k;
        float xv = (w >= 0 && w < NQ) ? x[b*NQ + w] : 0.f;
        float sx, cx; __sincosf(xv, &sx, &cx);   // RY(x)|0> Bloch = (sinx,0,cosx)
        m[k][0] = sx*bx[k][0] + cx*bz[k][0];
        m[k][1] = sx*bx[k][1] + cx*bz[k][1];
        m[k][2] = sx*bx[k][2] + cx*bz[k][2];
    }
    float dL = (i - 3 >= 0) ? m[0][2] : 1.f;   // D0 straddling CZ dressings
    float dR = (i + 3 < NQ) ? m[6][2] : 1.f;
    float v[5][4];
    #pragma unroll
    for (int k = 0; k < 5; k++) {
        v[k][0] = 1.f; v[k][1] = m[k+1][0]; v[k][2] = m[k+1][1]; v[k][3] = m[k+1][2];
    }
    v[0][1] *= dL; v[0][2] *= dL;
    v[4][1] *= dR; v[4][2] *= dR;

    const float4* T4 = reinterpret_cast<const float4*>(src);
    float z = 0.f;
    for (int a = 0; a < 4; a++) {
        float sa = 0.f;
        for (int q = 0; q < 4; q++) {
            float sb = 0.f;
            #pragma unroll
            for (int c = 0; c < 4; c++) {
                float sc = 0.f;
                #pragma unroll
                for (int d = 0; d < 4; d++) {
                    float4 t4 = T4[((a*4+q)*4+c)*4 + d];
                    sc += v[3][d] * (t4.x*v[4][0] + t4.y*v[4][1] + t4.z*v[4][2] + t4.w*v[4][3]);
                }
                sb += v[2][c] * sc;
            }
            sa += v[1][q] * sb;
        }
        z += v[0][a] * sa;
    }
    g_z[b * NQ + i] = z;
}

__global__ __launch_bounds__(128)
void fc_kernel(const float* __restrict__ fcw, const float* __restrict__ fcb,
               float* __restrict__ out)
{
    int idx = blockIdx.x * blockDim.x + threadIdx.x;
    if (idx >= BATCHSZ * NA) return;
    int b = idx / NA, a = idx % NA;
    float acc = fcb[a];
    #pragma unroll
    for (int k = 0; k < NQ; k++) acc += g_z[b*NQ + k] * fcw[a*NQ + k];
    out[idx] = acc;
}

extern "C" void kernel_launch(void* const* d_in, const int* in_sizes, int n_in,
                              void* d_out, int out_size) {
    const float* x   = (const float*)d_in[0];   // [512,16]
    const float* W   = (const float*)d_in[1];   // [4,16,3]
    const float* fcw = (const float*)d_in[2];   // [6,16]
    const float* fcb = (const float*)d_in[3];   // [6]
    float* out = (float*)d_out;                 // [512,6]
    (void)in_sizes; (void)n_in; (void)out_size;
    dim3 grid(NQ, BATCHSZ / 128);
    vqc_main<<<grid, 128>>>(x, W);
    fc_kernel<<<(BATCHSZ * NA + 127) / 128, 128>>>(fcw, fcb, out);
}

// round 4
// speedup vs baseline: 1.8207x; 1.0022x over previous
#include <cuda_runtime.h>
#include <math.h>

// PennyLaneBasicDQN: 16-qubit VQC (RY embed + 4x[Rot,CZ chain]) + linear head.
// Heisenberg light-cone + Pauli-transfer-matrix method (see R3), now fully
// fused into ONE kernel: the 16th CTA to finish each sample-chunk performs the
// FC head for that chunk (last-block pattern, counter reset for graph replay).

#define NQ 16
#define NA 6
#define BATCHSZ 512

__device__ float g_z[BATCHSZ * NQ];
__device__ int   g_cnt[4] = {0, 0, 0, 0};

struct C2 { float x, y; };
__device__ __forceinline__ C2 cmk(float a, float b){ C2 r; r.x=a; r.y=b; return r; }
__device__ __forceinline__ C2 cml(C2 a, C2 b){ return cmk(a.x*b.x - a.y*b.y, a.x*b.y + a.y*b.x); }
__device__ __forceinline__ C2 cad(C2 a, C2 b){ return cmk(a.x+b.x, a.y+b.y); }

// 4x4 real PTM of conjugation O -> U^dag O U:
//   M[q][p] = 0.5 * Re Tr[ sigma_q U^dag sigma_p U ]
__device__ void ptm_from_u(const C2 u[4], float* M) {
    C2 ud00 = cmk(u[0].x, -u[0].y), ud01 = cmk(u[2].x, -u[2].y);
    C2 ud10 = cmk(u[1].x, -u[1].y), ud11 = cmk(u[3].x, -u[3].y);
    #pragma unroll
    for (int p = 0; p < 4; p++) {
        C2 s00, s01, s10, s11;                 // sigma_p * U
        if (p == 0)      { s00=u[0]; s01=u[1]; s10=u[2]; s11=u[3]; }
        else if (p == 1) { s00=u[2]; s01=u[3]; s10=u[0]; s11=u[1]; }
        else if (p == 2) {                      // Y = [[0,-i],[i,0]]
            s00 = cmk( u[2].y, -u[2].x);        // -i*u10
            s01 = cmk( u[3].y, -u[3].x);
            s10 = cmk(-u[0].y,  u[0].x);        //  i*u00
            s11 = cmk(-u[1].y,  u[1].x);
        } else           { s00=u[0]; s01=u[1]; s10=cmk(-u[2].x,-u[2].y); s11=cmk(-u[3].x,-u[3].y); }
        C2 A00 = cad(cml(ud00, s00), cml(ud01, s10));
        C2 A01 = cad(cml(ud00, s01), cml(ud01, s11));
        C2 A10 = cad(cml(ud10, s00), cml(ud11, s10));
        C2 A11 = cad(cml(ud10, s01), cml(ud11, s11));
        M[0*4+p] = 0.5f*(A00.x + A11.x);
        M[1*4+p] = 0.5f*(A01.x + A10.x);
        M[2*4+p] = 0.5f*(A10.y - A01.y);        // Re(i*(A01-A10))
        M[3*4+p] = 0.5f*(A00.x - A11.x);
    }
}

// PennyLane Rot(phi,theta,omega) = RZ(omega) RY(theta) RZ(phi)
__device__ __forceinline__ void rot_u(const float* wp, C2 u[4]) {
    float phi = wp[0], th = wp[1], om = wp[2];
    float c, s; __sincosf(0.5f*th, &s, &c);
    float epx, epy, emx, emy;
    __sincosf(-0.5f*(phi+om), &epy, &epx);   // ep = exp(-i(phi+om)/2)
    __sincosf(-0.5f*(phi-om), &emy, &emx);   // em = exp(-i(phi-om)/2)
    u[0] = cmk( epx*c,  epy*c);              // m00 = ep*c
    u[1] = cmk(-emx*s,  emy*s);              // m01 = -conj(em)*s
    u[2] = cmk( emx*s,  emy*s);              // m10 = em*s
    u[3] = cmk( epx*c, -epy*c);              // m11 = conj(ep)*c
}

__global__ __launch_bounds__(128)
void vqc_fused(const float* __restrict__ x, const float* __restrict__ W,
               const float* __restrict__ fcw, const float* __restrict__ fcb,
               float* __restrict__ out)
{
    __shared__ __align__(16) float tA[1024];
    __shared__ __align__(16) float tB[1024];
    __shared__ float PT[15][16];          // conj-PTMs: layers 1..3 x window pos 0..4
    __shared__ float bx[7][3], bz[7][3];  // layer-0 Bloch columns for wires i-3..i+3
    __shared__ int s_elect;

    const int i     = blockIdx.x;         // measured qubit
    const int chunk = blockIdx.y;         // sample chunk (128 samples)
    const int tid   = threadIdx.x;
    const int b     = chunk * 128 + tid;

    if (tid < 15) {
        int l = 1 + tid / 5, a = tid % 5;
        int w = i - 2 + a;
        float* M = PT[tid];
        if (w >= 0 && w < NQ) {
            C2 u[4]; rot_u(W + (l*NQ + w)*3, u);
            ptm_from_u(u, M);
        } else {
            #pragma unroll
            for (int k = 0; k < 16; k++) M[k] = (k % 5 == 0) ? 1.f : 0.f;
        }
    } else if (tid >= 16 && tid < 23) {
        int k = tid - 16;
        int w = i - 3 + k;
        if (w >= 0 && w < NQ) {
            C2 u[4]; rot_u(W + w*3, u);                    // layer-0 Rot
            C2 v[4] = { cmk(u[0].x,-u[0].y), cmk(u[2].x,-u[2].y),
                        cmk(u[1].x,-u[1].y), cmk(u[3].x,-u[3].y) };  // U^dag
            float N[16]; ptm_from_u(v, N);                 // forward Bloch PTM
            bx[k][0]=N[4+1]; bx[k][1]=N[8+1]; bx[k][2]=N[12+1];
            bz[k][0]=N[4+3]; bz[k][1]=N[8+3]; bz[k][2]=N[12+3];
        } else {
            bx[k][0]=bx[k][1]=bx[k][2]=0.f;
            bz[k][0]=bz[k][1]=bz[k][2]=0.f;
        }
    }
    for (int j = tid; j < 1024; j += 128) tA[j] = (j == 48) ? 1.f : 0.f; // Z at pos 2
    __syncthreads();

    // per-sample Bloch vectors (compute early; x loads overlap stage latency)
    float m[7][3];
    #pragma unroll
    for (int k = 0; k < 7; k++) {
        int w = i - 3 + k;
        float xv = (w >= 0 && w < NQ) ? x[b*NQ + w] : 0.f;
        float sx, cx; __sincosf(xv, &sx, &cx);   // RY(x)|0> Bloch = (sinx,0,cosx)
        m[k][0] = sx*bx[k][0] + cx*bz[k][0];
        m[k][1] = sx*bx[k][1] + cx*bz[k][1];
        m[k][2] = sx*bx[k][2] + cx*bz[k][2];
    }

    // Backward conjugation: M(R3), CZ(D2), M(R2), CZ(D1), M(R1), CZ(D0)
    float* src = tA; float* dst = tB;
    for (int l = 3; l >= 1; l--) {
        for (int a = 0; a < 5; a++) {
            const float* M = PT[(l-1)*5 + a];
            const int s = 1 << (2*(4-a));      // axis stride: 256,64,16,4,1
            for (int g = tid; g < 256; g += 128) {
                int base = (g / s) * (4*s) + (g % s);
                float c0 = src[base], c1 = src[base+s], c2 = src[base+2*s], c3 = src[base+3*s];
                dst[base]     = M[0] *c0 + M[1] *c1 + M[2] *c2 + M[3] *c3;
                dst[base+s]   = M[4] *c0 + M[5] *c1 + M[6] *c2 + M[7] *c3;
                dst[base+2*s] = M[8] *c0 + M[9] *c1 + M[10]*c2 + M[11]*c3;
                dst[base+3*s] = M[12]*c0 + M[13]*c1 + M[14]*c2 + M[15]*c3;
            }
            __syncthreads();
            float* t = src; src = dst; dst = t;
        }
        // CZ chain: np = xr? p^3:p ; nq = xl? q^3:q ; sign -1 iff xl&&xr&&p!=q
        for (int e = tid; e < 1024; e += 128) {
            int p[5] = {(e>>8)&3, (e>>6)&3, (e>>4)&3, (e>>2)&3, e&3};
            float sg = src[e];
            #pragma unroll
            for (int a = 0; a < 4; a++) {
                int wl = i - 2 + a;
                if (wl >= 0 && wl + 1 < NQ) {
                    int pa = p[a], pb = p[a+1];
                    bool xl = (pa==1)||(pa==2), xr = (pb==1)||(pb==2);
                    if (xl && xr && pa != pb) sg = -sg;
                    if (xr) p[a]   = pa ^ 3;
                    if (xl) p[a+1] = pb ^ 3;
                }
            }
            int di = (p[0]<<8)|(p[1]<<6)|(p[2]<<4)|(p[3]<<2)|p[4];
            dst[di] = sg;
        }
        __syncthreads();
        float* t = src; src = dst; dst = t;
    }
    // 18 stages (even) -> final tensor in `src`

    // ---- per-sample contraction ----
    float dL = (i - 3 >= 0) ? m[0][2] : 1.f;   // D0 straddling CZ dressings
    float dR = (i + 3 < NQ) ? m[6][2] : 1.f;
    float v[5][4];
    #pragma unroll
    for (int k = 0; k < 5; k++) {
        v[k][0] = 1.f; v[k][1] = m[k+1][0]; v[k][2] = m[k+1][1]; v[k][3] = m[k+1][2];
    }
    v[0][1] *= dL; v[0][2] *= dL;
    v[4][1] *= dR; v[4][2] *= dR;

    const float4* T4 = reinterpret_cast<const float4*>(src);
    float z = 0.f;
    #pragma unroll
    for (int a = 0; a < 4; a++) {
        float sa = 0.f;
        #pragma unroll
        for (int q = 0; q < 4; q++) {
            float sb = 0.f;
            #pragma unroll
            for (int c = 0; c < 4; c++) {
                float sc = 0.f;
                #pragma unroll
                for (int d = 0; d < 4; d++) {
                    float4 t4 = T4[((a*4+q)*4+c)*4 + d];
                    sc += v[3][d] * (t4.x*v[4][0] + t4.y*v[4][1] + t4.z*v[4][2] + t4.w*v[4][3]);
                }
                sb += v[2][c] * sc;
            }
            sa += v[1][q] * sb;
        }
        z += v[0][a] * sa;
    }
    g_z[b * NQ + i] = z;

    // ---- fused FC head: last CTA of this chunk does the 128x6 GEMV ----
    __syncthreads();                       // all g_z stores of this CTA issued
    if (tid == 0) {
        __threadfence();                   // release: make block's stores visible
        int old = atomicAdd(&g_cnt[chunk], 1);
        int e = (old == 15);
        if (e) {
            __threadfence();               // acquire: see other CTAs' stores
            atomicExch(&g_cnt[chunk], 0);  // reset for next graph replay
        }
        s_elect = e;
    }
    __syncthreads();
    if (s_elect) {
        float zz[NQ];
        #pragma unroll
        for (int k = 0; k < NQ; k++) zz[k] = __ldcg(&g_z[b*NQ + k]);
        #pragma unroll
        for (int a = 0; a < NA; a++) {
            float acc = fcb[a];
            #pragma unroll
            for (int k = 0; k < NQ; k++) acc += zz[k] * fcw[a*NQ + k];
            out[b*NA + a] = acc;
        }
    }
}

extern "C" void kernel_launch(void* const* d_in, const int* in_sizes, int n_in,
                              void* d_out, int out_size) {
    const float* x   = (const float*)d_in[0];   // [512,16]
    const float* W   = (const float*)d_in[1];   // [4,16,3]
    const float* fcw = (const float*)d_in[2];   // [6,16]
    const float* fcb = (const float*)d_in[3];   // [6]
    float* out = (float*)d_out;                 // [512,6]
    (void)in_sizes; (void)n_in; (void)out_size;
    dim3 grid(NQ, BATCHSZ / 128);
    vqc_fused<<<grid, 128>>>(x, W, fcw, fcb, out);
}